// round 4
// baseline (speedup 1.0000x reference)
#include <cuda_runtime.h>
#include <cuda_bf16.h>

// ---------------------------------------------------------------------------
// MHCLayerAITER: out[b,i,c] = sum_j M[i][j]*x[b,j,c] + 2*sig(H_post[i]) * y[b,c]
//   where y[b,c] = bf16(x_agg[b,c]) / rms_b * bf16(w[c]),
//         x_agg[b,c] = sum_n sig(H_pre[n]) * x[b,n,c],
//         rms_b = sqrt(mean_c bf16(x_agg)^2 + 1e-6),
//         M = sinkhorn_knopp(exp(H_res), 3 iters, eps=1e-6)
// Shapes: B=8192, n=4, C=2048. HBM-bound: 256MB in + 256MB out.
// ---------------------------------------------------------------------------

namespace {
constexpr int kB = 8192;
constexpr int kN = 4;
constexpr int kC = 2048;
constexpr int kThreads = 256;
constexpr int kC4 = kC / 4;            // 512 float4 per stream per row
constexpr int kVec = kC4 / kThreads;   // 2 float4 chunks per thread
constexpr float kEps = 1e-6f;
}

// Precomputed parameters: M (16) | sigmoid(H_pre) (4) | 2*sigmoid(H_post) (4)
__device__ float g_params[24];

// ---------------------------------------------------------------------------
// Prologue: tiny Sinkhorn + activations, computed once. 1 block / 1 thread.
// ---------------------------------------------------------------------------
__global__ void mhc_setup_kernel(const float* __restrict__ H_pre,
                                 const float* __restrict__ H_post,
                                 const float* __restrict__ H_res) {
    float P[4][4];
#pragma unroll
    for (int i = 0; i < 4; ++i)
#pragma unroll
        for (int j = 0; j < 4; ++j)
            P[i][j] = expf(H_res[i * 4 + j]);

#pragma unroll
    for (int it = 0; it < 3; ++it) {
        // row normalize (sum over axis=-1)
#pragma unroll
        for (int i = 0; i < 4; ++i) {
            float s = P[i][0] + P[i][1] + P[i][2] + P[i][3] + kEps;
#pragma unroll
            for (int j = 0; j < 4; ++j) P[i][j] = P[i][j] / s;
        }
        // column normalize (sum over axis=-2)
#pragma unroll
        for (int j = 0; j < 4; ++j) {
            float s = P[0][j] + P[1][j] + P[2][j] + P[3][j] + kEps;
#pragma unroll
            for (int i = 0; i < 4; ++i) P[i][j] = P[i][j] / s;
        }
    }

#pragma unroll
    for (int i = 0; i < 4; ++i)
#pragma unroll
        for (int j = 0; j < 4; ++j)
            g_params[i * 4 + j] = P[i][j];
#pragma unroll
    for (int n = 0; n < 4; ++n)
        g_params[16 + n] = 1.0f / (1.0f + expf(-H_pre[n]));
#pragma unroll
    for (int n = 0; n < 4; ++n)
        g_params[20 + n] = 2.0f / (1.0f + expf(-H_post[n]));
}

// ---------------------------------------------------------------------------
// Main fused kernel. One CTA per batch row. x is loaded once into registers
// and reused for both the aggregation and the 4x4 stream mix.
// ---------------------------------------------------------------------------
__global__ __launch_bounds__(kThreads) void mhc_main_kernel(
    const float4* __restrict__ x,      // [B, n, C/4]
    const float4* __restrict__ w,      // [C/4]
    float4* __restrict__ out) {        // [B, n, C/4]
    const int b = blockIdx.x;
    const int t = threadIdx.x;

    // Broadcast-load precomputed params (uniform address -> 1 wavefront each).
    float M[4][4], hpre[4], hpost[4];
#pragma unroll
    for (int i = 0; i < 4; ++i)
#pragma unroll
        for (int j = 0; j < 4; ++j)
            M[i][j] = g_params[i * 4 + j];
#pragma unroll
    for (int n = 0; n < 4; ++n) hpre[n] = g_params[16 + n];
#pragma unroll
    for (int n = 0; n < 4; ++n) hpost[n] = g_params[20 + n];

    const size_t base = (size_t)b * (kN * kC4);

    // ---- Load all 4 streams for this thread's 8 channels (front-batched) ----
    float xr[kN][kVec * 4];
#pragma unroll
    for (int k = 0; k < kVec; ++k) {
        const int c4 = t + k * kThreads;
#pragma unroll
        for (int n = 0; n < kN; ++n) {
            float4 v = x[base + (size_t)n * kC4 + c4];
            xr[n][k * 4 + 0] = v.x;
            xr[n][k * 4 + 1] = v.y;
            xr[n][k * 4 + 2] = v.z;
            xr[n][k * 4 + 3] = v.w;
        }
    }

    // ---- Weight (L2/L1-resident after first block on each SM) ----
    float wr[kVec * 4];
#pragma unroll
    for (int k = 0; k < kVec; ++k) {
        float4 wv = w[t + k * kThreads];
        wr[k * 4 + 0] = __bfloat162float(__float2bfloat16_rn(wv.x));
        wr[k * 4 + 1] = __bfloat162float(__float2bfloat16_rn(wv.y));
        wr[k * 4 + 2] = __bfloat162float(__float2bfloat16_rn(wv.z));
        wr[k * 4 + 3] = __bfloat162float(__float2bfloat16_rn(wv.w));
    }

    // ---- Aggregate streams; round through bf16; accumulate sum of squares ----
    float aggb[kVec * 4];
    float lsum = 0.0f;
#pragma unroll
    for (int e = 0; e < kVec * 4; ++e) {
        float a = 0.0f;
#pragma unroll
        for (int n = 0; n < kN; ++n)
            a = fmaf(hpre[n], xr[n][e], a);
        float ab = __bfloat162float(__float2bfloat16_rn(a));
        aggb[e] = ab;
        lsum = fmaf(ab, ab, lsum);
    }

    // ---- Block reduction of sum of squares over C=2048 ----
#pragma unroll
    for (int off = 16; off > 0; off >>= 1)
        lsum += __shfl_xor_sync(0xFFFFFFFFu, lsum, off);

    __shared__ float s_warp[kThreads / 32];
    __shared__ float s_rinv;
    const int wid = t >> 5;
    const int lane = t & 31;
    if (lane == 0) s_warp[wid] = lsum;
    __syncthreads();
    if (t == 0) {
        float s = 0.0f;
#pragma unroll
        for (int i = 0; i < kThreads / 32; ++i) s += s_warp[i];
        float rms = sqrtf(s * (1.0f / (float)kC) + kEps);
        s_rinv = 1.0f / rms;
    }
    __syncthreads();
    const float rinv = s_rinv;

    // ---- y_norm and output: out[i] = sum_j M[i][j]*x[j] + hpost[i]*y ----
    float y[kVec * 4];
#pragma unroll
    for (int e = 0; e < kVec * 4; ++e)
        y[e] = aggb[e] * rinv * wr[e];

#pragma unroll
    for (int i = 0; i < kN; ++i) {
#pragma unroll
        for (int k = 0; k < kVec; ++k) {
            const int c4 = t + k * kThreads;
            float4 o;
            float r[4];
#pragma unroll
            for (int q = 0; q < 4; ++q) {
                const int e = k * 4 + q;
                float acc = hpost[i] * y[e];
#pragma unroll
                for (int j = 0; j < kN; ++j)
                    acc = fmaf(M[i][j], xr[j][e], acc);
                r[q] = acc;
            }
            o.x = r[0]; o.y = r[1]; o.z = r[2]; o.w = r[3];
            out[base + (size_t)i * kC4 + c4] = o;
        }
    }
}

// ---------------------------------------------------------------------------
// Launch. Inputs (metadata order): x, rmsnorm_weight, H_pre, H_post, H_res.
// ---------------------------------------------------------------------------
extern "C" void kernel_launch(void* const* d_in, const int* in_sizes, int n_in,
                              void* d_out, int out_size) {
    const float* x      = (const float*)d_in[0];
    const float* w      = (const float*)d_in[1];
    const float* H_pre  = (const float*)d_in[2];
    const float* H_post = (const float*)d_in[3];
    const float* H_res  = (const float*)d_in[4];
    float* out = (float*)d_out;

    mhc_setup_kernel<<<1, 1>>>(H_pre, H_post, H_res);
    mhc_main_kernel<<<kB, kThreads>>>(
        (const float4*)x, (const float4*)w, (float4*)out);
}

// round 5
// speedup vs baseline: 1.0769x; 1.0769x over previous
#include <cuda_runtime.h>
#include <cuda_bf16.h>

// ---------------------------------------------------------------------------
// MHCLayerAITER fused single-kernel version.
// out[b,i,c] = sum_j M[i][j]*x[b,j,c] + 2*sig(H_post[i]) * y[b,c]
//   y[b,c]   = bf16(x_agg[b,c]) / rms_b * bf16(w[c])
//   x_agg    = sum_n sig(H_pre[n]) * x[b,n,c]
//   rms_b    = sqrt(mean_c bf16(x_agg)^2 + 1e-6)
//   M        = sinkhorn_knopp(exp(H_res), 3 iters, eps=1e-6)
// B=8192, n=4, C=2048. HBM-bound: 268MB in + 268MB out.
// The Sinkhorn prologue is computed redundantly per block by warp 0 via
// shuffle butterflies, hidden behind the front-batched x loads — this removes
// the separate setup-kernel graph node (~12 us of launch/drain overhead).
// ---------------------------------------------------------------------------

namespace {
constexpr int kB = 8192;
constexpr int kN = 4;
constexpr int kC = 2048;
constexpr int kThreads = 256;
constexpr int kC4 = kC / 4;            // 512 float4 per stream per row
constexpr int kVec = kC4 / kThreads;   // 2 float4 chunks per thread
constexpr float kEps = 1e-6f;
}

__global__ __launch_bounds__(kThreads) void mhc_fused_kernel(
    const float4* __restrict__ x,      // [B, n, C/4]
    const float4* __restrict__ w,      // [C/4]
    const float*  __restrict__ H_pre,  // [4]
    const float*  __restrict__ H_post, // [4]
    const float*  __restrict__ H_res,  // [4,4]
    float4* __restrict__ out) {        // [B, n, C/4]
    const int b = blockIdx.x;
    const int t = threadIdx.x;

    __shared__ float s_params[24];     // M[16] | sig(H_pre)[4] | 2*sig(H_post)[4]
    __shared__ float s_warp[kThreads / 32];
    __shared__ float s_rinv;

    const size_t base = (size_t)b * (kN * kC4);

    // ---- Front-batched loads: all 4 streams, this thread's 8 channels ------
    float xr[kN][kVec * 4];
#pragma unroll
    for (int k = 0; k < kVec; ++k) {
        const int c4 = t + k * kThreads;
#pragma unroll
        for (int n = 0; n < kN; ++n) {
            float4 v = x[base + (size_t)n * kC4 + c4];
            xr[n][k * 4 + 0] = v.x;
            xr[n][k * 4 + 1] = v.y;
            xr[n][k * 4 + 2] = v.z;
            xr[n][k * 4 + 3] = v.w;
        }
    }

    // ---- Weight (L2-resident; bf16-round to match reference) --------------
    float wr[kVec * 4];
#pragma unroll
    for (int k = 0; k < kVec; ++k) {
        float4 wv = w[t + k * kThreads];
        wr[k * 4 + 0] = __bfloat162float(__float2bfloat16_rn(wv.x));
        wr[k * 4 + 1] = __bfloat162float(__float2bfloat16_rn(wv.y));
        wr[k * 4 + 2] = __bfloat162float(__float2bfloat16_rn(wv.z));
        wr[k * 4 + 3] = __bfloat162float(__float2bfloat16_rn(wv.w));
    }

    // ---- Warp 0: Sinkhorn-Knopp on exp(H_res) + activations, via shuffles.
    // Lane l (<16) owns P[l/4][l%4]. Row sum = butterfly over offsets {1,2}
    // (lanes within a quad share row i). Col sum = offsets {4,8} (lanes with
    // equal l%4 share column j). Lanes 16-31 run with p=exp(0)=1: their
    // butterflies stay inside the upper half and never pollute lanes 0-15.
    // This work overlaps the outstanding x LDGs above.
    if (t < 32) {
        const int lane = t;
        float h = (lane < 16) ? H_res[lane] : 0.0f;
        float p = expf(h);
#pragma unroll
        for (int it = 0; it < 3; ++it) {
            float s = p;
            s += __shfl_xor_sync(0xFFFFFFFFu, s, 1);
            s += __shfl_xor_sync(0xFFFFFFFFu, s, 2);
            p = p / (s + kEps);          // row normalize
            s = p;
            s += __shfl_xor_sync(0xFFFFFFFFu, s, 4);
            s += __shfl_xor_sync(0xFFFFFFFFu, s, 8);
            p = p / (s + kEps);          // column normalize
        }
        if (lane < 16) {
            s_params[lane] = p;
        } else if (lane < 20) {
            s_params[lane] = 1.0f / (1.0f + expf(-H_pre[lane - 16]));
        } else if (lane < 24) {
            s_params[lane] = 2.0f / (1.0f + expf(-H_post[lane - 20]));
        }
    }
    __syncthreads();

    float M[4][4], hpre[4], hpost[4];
#pragma unroll
    for (int i = 0; i < 4; ++i)
#pragma unroll
        for (int j = 0; j < 4; ++j)
            M[i][j] = s_params[i * 4 + j];
#pragma unroll
    for (int n = 0; n < 4; ++n) hpre[n] = s_params[16 + n];
#pragma unroll
    for (int n = 0; n < 4; ++n) hpost[n] = s_params[20 + n];

    // ---- Aggregate streams; round through bf16; sum of squares ------------
    float aggb[kVec * 4];
    float lsum = 0.0f;
#pragma unroll
    for (int e = 0; e < kVec * 4; ++e) {
        float a = 0.0f;
#pragma unroll
        for (int n = 0; n < kN; ++n)
            a = fmaf(hpre[n], xr[n][e], a);
        float ab = __bfloat162float(__float2bfloat16_rn(a));
        aggb[e] = ab;
        lsum = fmaf(ab, ab, lsum);
    }

    // ---- Block reduction over C=2048 ---------------------------------------
#pragma unroll
    for (int off = 16; off > 0; off >>= 1)
        lsum += __shfl_xor_sync(0xFFFFFFFFu, lsum, off);

    const int wid = t >> 5;
    const int lane = t & 31;
    if (lane == 0) s_warp[wid] = lsum;
    __syncthreads();
    if (t == 0) {
        float s = 0.0f;
#pragma unroll
        for (int i = 0; i < kThreads / 32; ++i) s += s_warp[i];
        float rms = sqrtf(s * (1.0f / (float)kC) + kEps);
        s_rinv = 1.0f / rms;
    }
    __syncthreads();
    const float rinv = s_rinv;

    // ---- y_norm and output: out[i] = sum_j M[i][j]*x[j] + hpost[i]*y -------
    float y[kVec * 4];
#pragma unroll
    for (int e = 0; e < kVec * 4; ++e)
        y[e] = aggb[e] * rinv * wr[e];

#pragma unroll
    for (int i = 0; i < kN; ++i) {
#pragma unroll
        for (int k = 0; k < kVec; ++k) {
            const int c4 = t + k * kThreads;
            float4 o;
            float r[4];
#pragma unroll
            for (int q = 0; q < 4; ++q) {
                const int e = k * 4 + q;
                float acc = hpost[i] * y[e];
#pragma unroll
                for (int j = 0; j < kN; ++j)
                    acc = fmaf(M[i][j], xr[j][e], acc);
                r[q] = acc;
            }
            o.x = r[0]; o.y = r[1]; o.z = r[2]; o.w = r[3];
            out[base + (size_t)i * kC4 + c4] = o;
        }
    }
}

// ---------------------------------------------------------------------------
// Launch. Inputs (metadata order): x, rmsnorm_weight, H_pre, H_post, H_res.
// Single graph node — no prologue kernel.
// ---------------------------------------------------------------------------
extern "C" void kernel_launch(void* const* d_in, const int* in_sizes, int n_in,
                              void* d_out, int out_size) {
    const float* x      = (const float*)d_in[0];
    const float* w      = (const float*)d_in[1];
    const float* H_pre  = (const float*)d_in[2];
    const float* H_post = (const float*)d_in[3];
    const float* H_res  = (const float*)d_in[4];
    float* out = (float*)d_out;

    mhc_fused_kernel<<<kB, kThreads>>>(
        (const float4*)x, (const float4*)w, H_pre, H_post, H_res,
        (float4*)out);
}